// round 15
// baseline (speedup 1.0000x reference)
#include <cuda_runtime.h>
#include <cuda_fp16.h>
#include <cstddef>
#include <cstdint>

#define BDIM 128
#define LDIM 512
#define EHD  256
#define DHD  256
#define YD   8

// ---------------- device scratch (static, allocation-free) ----------------
__device__ __half g_projh[(size_t)BDIM * LDIM * EHD]; // 32MB fp16 proj
__device__ __half g_xh[(size_t)BDIM * LDIM * EHD];    // 32MB fp16 x
__device__ __half g_wh[EHD * EHD];                    // W1x fp16 [n][k] (GEMM B)
__device__ uint2  g_whcT4[128 * 256];                 // W1[h,c] packed: [k4][j] 4k per j
__device__ uint4  g_whh4[128 * 256];                  // Whh packed: [k2][j] 4gates x k-pair
__device__ float4 g_wih4[8 * 256];                    // Wih packed: [y][j] 4 gates
__device__ float4 g_bias4[256];                       // (bih+bhh) per j, 4 gates

// ---------------- math helpers ----------------
__device__ __forceinline__ float tanh_hw(float x) {
    float y; asm("tanh.approx.f32 %0, %1;" : "=f"(y) : "f"(x)); return y;
}
__device__ __forceinline__ float fast_tanh(float x) { // accurate, for LSTM
    float e = __expf(2.0f * x);
    return 1.0f - __fdividef(2.0f, e + 1.0f);
}
__device__ __forceinline__ float fast_sig(float x) {
    return __fdividef(1.0f, 1.0f + __expf(-x));
}
__device__ __forceinline__ float warp_sum(float v) {
    #pragma unroll
    for (int o = 16; o > 0; o >>= 1) v += __shfl_xor_sync(0xffffffffu, v, o);
    return v;
}
__device__ __forceinline__ float warp_max(float v) {
    #pragma unroll
    for (int o = 16; o > 0; o >>= 1) v = fmaxf(v, __shfl_xor_sync(0xffffffffu, v, o));
    return v;
}
__device__ __forceinline__ void barA() {   // group-A barrier: warps 0-7 (256 thr)
    asm volatile("bar.sync 1, 256;" ::: "memory");
}
__device__ __forceinline__ void mma_f16(float c[4], const uint32_t a[4],
                                        const uint32_t b[2]) {
    asm volatile(
        "mma.sync.aligned.m16n8k16.row.col.f32.f16.f16.f32 "
        "{%0,%1,%2,%3}, {%4,%5,%6,%7}, {%8,%9}, {%0,%1,%2,%3};\n"
        : "+f"(c[0]), "+f"(c[1]), "+f"(c[2]), "+f"(c[3])
        : "r"(a[0]), "r"(a[1]), "r"(a[2]), "r"(a[3]), "r"(b[0]), "r"(b[1]));
}

// ---------------- converts ----------------
__global__ __launch_bounds__(256) void k_convx(const float* __restrict__ x) {
    const int n4 = (BDIM * LDIM * EHD) / 4;
    for (int i = blockIdx.x * blockDim.x + threadIdx.x; i < n4;
         i += gridDim.x * blockDim.x) {
        float4 v = *(const float4*)(x + (size_t)i * 4);
        __half2 p0 = __floats2half2_rn(v.x, v.y);
        __half2 p1 = __floats2half2_rn(v.z, v.w);
        uint2 o; o.x = *(uint32_t*)&p0; o.y = *(uint32_t*)&p1;
        *(uint2*)(g_xh + (size_t)i * 4) = o;
    }
}

// merged weight converts: blocks [0,64) g_wh; [64,192) whcT4; [192,320) whh4;
// block 320: wih4 + bias4.
__global__ __launch_bounds__(256) void k_convs(const float* __restrict__ W1,
                                               const float* __restrict__ Whh,
                                               const float* __restrict__ Wih,
                                               const float* __restrict__ bih,
                                               const float* __restrict__ bhh) {
    const int blk = blockIdx.x, tid = threadIdx.x;
    if (blk < 64) {
        int i = blk * 256 + tid;              // 16384 float4
        int row = i >> 6, c4 = (i & 63) * 4;
        float4 v = *(const float4*)(W1 + (size_t)row * 768 + 512 + c4);
        __half2 p0 = __floats2half2_rn(v.x, v.y);
        __half2 p1 = __floats2half2_rn(v.z, v.w);
        uint2 o; o.x = *(uint32_t*)&p0; o.y = *(uint32_t*)&p1;
        *(uint2*)(g_wh + (size_t)row * 256 + c4) = o;
    } else if (blk < 192) {
        int idx = (blk - 64) * 256 + tid;     // 32768: k4 x j
        int k4 = idx >> 8, j = idx & 255;
        const float* w = W1 + (size_t)j * 768 + 4 * k4;   // columns [0,512): h then c
        __half2 p0 = __floats2half2_rn(w[0], w[1]);
        __half2 p1 = __floats2half2_rn(w[2], w[3]);
        uint2 o; o.x = *(uint32_t*)&p0; o.y = *(uint32_t*)&p1;
        g_whcT4[idx] = o;
    } else if (blk < 320) {
        int idx = (blk - 192) * 256 + tid;    // 32768: k2 x j
        int k2 = idx >> 8, j = idx & 255;
        uint4 o;
        #pragma unroll
        for (int g = 0; g < 4; g++) {
            const float* w = Whh + (size_t)(g * 256 + j) * 256 + 2 * k2;
            __half2 p = __floats2half2_rn(w[0], w[1]);
            ((uint32_t*)&o)[g] = *(uint32_t*)&p;
        }
        g_whh4[idx] = o;
    } else {
        for (int idx = tid; idx < 2048; idx += 256) {     // wih4: y x j
            int y = idx >> 8, j = idx & 255;
            g_wih4[idx] = make_float4(Wih[(size_t)(0 * 256 + j) * 8 + y],
                                      Wih[(size_t)(1 * 256 + j) * 8 + y],
                                      Wih[(size_t)(2 * 256 + j) * 8 + y],
                                      Wih[(size_t)(3 * 256 + j) * 8 + y]);
        }
        if (tid < 256)
            g_bias4[tid] = make_float4(bih[tid] + bhh[tid],
                                       bih[256 + tid] + bhh[256 + tid],
                                       bih[512 + tid] + bhh[512 + tid],
                                       bih[768 + tid] + bhh[768 + tid]);
    }
}

// ---------------- tensor-core proj GEMM (measured-good, unchanged) -----------
__global__ __launch_bounds__(256) void k_projmma() {
    __shared__ __half As[128][72];
    __shared__ __half Bs[128][72];
    const int bm = blockIdx.y * 128;
    const int bn = blockIdx.x * 128;
    const int tid = threadIdx.x;
    const int wid = tid >> 5, ln = tid & 31;
    const int wm = wid & 3, wn = wid >> 2;
    const int g = ln >> 2, tg2 = (ln & 3) * 2;

    float acc[2][8][4];
    #pragma unroll
    for (int mi = 0; mi < 2; mi++)
        #pragma unroll
        for (int ni = 0; ni < 8; ni++)
            #pragma unroll
            for (int q = 0; q < 4; q++) acc[mi][ni][q] = 0.0f;

    for (int kc = 0; kc < 4; kc++) {
        const int kb = kc * 64;
        #pragma unroll
        for (int it = 0; it < 4; it++) {
            int idx = it * 256 + tid;
            int row = idx >> 3;
            int col8 = (idx & 7) * 8;
            uint4 av = *(const uint4*)(g_xh + (size_t)(bm + row) * 256 + kb + col8);
            uint4 bv = *(const uint4*)(g_wh + (size_t)(bn + row) * 256 + kb + col8);
            *(uint4*)&As[row][col8] = av;
            *(uint4*)&Bs[row][col8] = bv;
        }
        __syncthreads();

        #pragma unroll
        for (int ks = 0; ks < 64; ks += 16) {
            uint32_t a[2][4], bf[8][2];
            #pragma unroll
            for (int mi = 0; mi < 2; mi++) {
                int mb = wm * 32 + mi * 16;
                a[mi][0] = *(const uint32_t*)&As[mb + g][ks + tg2];
                a[mi][1] = *(const uint32_t*)&As[mb + g + 8][ks + tg2];
                a[mi][2] = *(const uint32_t*)&As[mb + g][ks + tg2 + 8];
                a[mi][3] = *(const uint32_t*)&As[mb + g + 8][ks + tg2 + 8];
            }
            #pragma unroll
            for (int ni = 0; ni < 8; ni++) {
                int nb = wn * 64 + ni * 8;
                bf[ni][0] = *(const uint32_t*)&Bs[nb + g][ks + tg2];
                bf[ni][1] = *(const uint32_t*)&Bs[nb + g][ks + tg2 + 8];
            }
            #pragma unroll
            for (int mi = 0; mi < 2; mi++)
                #pragma unroll
                for (int ni = 0; ni < 8; ni++)
                    mma_f16(acc[mi][ni], a[mi], bf[ni]);
        }
        __syncthreads();
    }

    #pragma unroll
    for (int mi = 0; mi < 2; mi++) {
        int r0 = bm + wm * 32 + mi * 16 + g;
        #pragma unroll
        for (int ni = 0; ni < 8; ni++) {
            int col = bn + wn * 64 + ni * 8 + tg2;
            __half2 p0 = __floats2half2_rn(acc[mi][ni][0], acc[mi][ni][1]);
            __half2 p1 = __floats2half2_rn(acc[mi][ni][2], acc[mi][ni][3]);
            *(uint32_t*)&g_projh[(size_t)r0 * 256 + col] = *(uint32_t*)&p0;
            *(uint32_t*)&g_projh[(size_t)(r0 + 8) * 256 + col] = *(uint32_t*)&p1;
        }
    }
}

// ---------------- warp-specialized persistent per-batch decode ---------------
// One block per batch, 512 threads. Warps 0-7 (A): attention chain with named
// barrier 1. Warps 8-15 (B): Whh partial gates, overlapped. __syncthreads joins.
__global__ __launch_bounds__(512) void k_decode(
    const float* __restrict__ b1,   const float* __restrict__ w2,
    const float* __restrict__ Wfc,  const float* __restrict__ bfc,
    const float* __restrict__ Wfin, const float* __restrict__ bfin,
    const float* __restrict__ yh,   float* __restrict__ out, int T)
{
    __shared__ float hc_s[512];            // h = [0,256), c = [256,512)
    __shared__ float u_s[EHD], w2_s[EHD], b1_s[EHD];
    __shared__ float sc[LDIM];
    __shared__ float red[16];
    __shared__ float part4[4][EHD];
    __shared__ float ctx_s[EHD];
    __shared__ float yp_s[YD], yt_s[YD];
    __shared__ float pg[4][EHD];           // partial gates from B
    __shared__ float wfc_s[8 * 264], wfin_s[8 * 512];
    __shared__ float bfc_s[YD], bfin_s[YD];

    const int b = blockIdx.x;
    const int tid = threadIdx.x;
    const int w = tid >> 5, ln = tid & 31;

    // one-time smem staging
    if (tid < 512) hc_s[tid] = 0.0f;
    if (tid < 256) { w2_s[tid] = w2[tid]; b1_s[tid] = b1[tid]; }
    for (int i = tid; i < 8 * 264; i += 512) wfc_s[i] = Wfc[i];
    for (int i = tid; i < 8 * 512; i += 512) wfin_s[i] = Wfin[i];
    if (tid < YD) { yp_s[tid] = yh[b * YD + tid]; bfc_s[tid] = bfc[tid]; bfin_s[tid] = bfin[tid]; }
    __syncthreads();

    for (int t = 0; t < T; t++) {
        if (tid < 256) {
            // ============ group A: attention chain ============
            // ---- u[j] = b1[j] + W1hc[j,:].[h,c] ----
            {
                const int j = tid;
                float acc = b1_s[j];
                #pragma unroll 4
                for (int k4 = 0; k4 < 128; k4++) {
                    uint2 wv = g_whcT4[k4 * 256 + j];
                    float2 f0 = __half22float2(*(__half2*)&wv.x);
                    float2 f1 = __half22float2(*(__half2*)&wv.y);
                    int k = k4 << 2;
                    acc += f0.x * hc_s[k] + f0.y * hc_s[k + 1]
                         + f1.x * hc_s[k + 2] + f1.y * hc_s[k + 3];
                }
                u_s[j] = acc;
            }
            barA();

            // ---- scores: warp w handles 64 l ----
            {
                const int j0 = ln << 3;
                const float uw0 = u_s[j0],     uw1 = u_s[j0 + 1], uw2 = u_s[j0 + 2], uw3 = u_s[j0 + 3];
                const float uw4 = u_s[j0 + 4], uw5 = u_s[j0 + 5], uw6 = u_s[j0 + 6], uw7 = u_s[j0 + 7];
                const float w20 = w2_s[j0],     w21 = w2_s[j0 + 1], w22 = w2_s[j0 + 2], w23 = w2_s[j0 + 3];
                const float w24 = w2_s[j0 + 4], w25 = w2_s[j0 + 5], w26 = w2_s[j0 + 6], w27 = w2_s[j0 + 7];
                for (int li = 0; li < 64; li++) {
                    int l = w * 64 + li;
                    const uint4* p = (const uint4*)(g_projh + ((size_t)(b * LDIM + l)) * EHD);
                    uint4 pv = p[ln];
                    float2 f0 = __half22float2(*(__half2*)&pv.x);
                    float2 f1 = __half22float2(*(__half2*)&pv.y);
                    float2 f2 = __half22float2(*(__half2*)&pv.z);
                    float2 f3 = __half22float2(*(__half2*)&pv.w);
                    float s = w20 * tanh_hw(f0.x + uw0) + w21 * tanh_hw(f0.y + uw1)
                            + w22 * tanh_hw(f1.x + uw2) + w23 * tanh_hw(f1.y + uw3)
                            + w24 * tanh_hw(f2.x + uw4) + w25 * tanh_hw(f2.y + uw5)
                            + w26 * tanh_hw(f3.x + uw6) + w27 * tanh_hw(f3.y + uw7);
                    s = warp_sum(s);
                    if (ln == 0) sc[l] = s;
                }
            }
            barA();

            // ---- softmax over 512 (2 vals/thread) ----
            float rinv;
            {
                float v0 = sc[tid], v1 = sc[tid + 256];
                float m = warp_max(fmaxf(v0, v1));
                if (ln == 0) red[w] = m;
                barA();
                float mx = red[0];
                #pragma unroll
                for (int i = 1; i < 8; i++) mx = fmaxf(mx, red[i]);
                float e0 = __expf(v0 - mx), e1 = __expf(v1 - mx);
                sc[tid] = e0; sc[tid + 256] = e1;
                float ss = warp_sum(e0 + e1);
                if (ln == 0) red[8 + w] = ss;
                barA();
                float tot = red[8] + red[9] + red[10] + red[11]
                          + red[12] + red[13] + red[14] + red[15];
                rinv = __fdividef(1.0f, tot);
            }

            // ---- context: thread = (j-quad, l-quarter) ----
            {
                int jq = (tid & 63) * 4, lq = tid >> 6;
                const __half* xb = g_xh + ((size_t)(b * LDIM) + lq * 128) * EHD + jq;
                float a0 = 0.0f, a1 = 0.0f, a2 = 0.0f, a3 = 0.0f;
                #pragma unroll 4
                for (int l = 0; l < 128; l++) {
                    uint2 pv = *(const uint2*)(xb + (size_t)l * EHD);
                    float2 f0 = __half22float2(*(__half2*)&pv.x);
                    float2 f1 = __half22float2(*(__half2*)&pv.y);
                    float wv = sc[lq * 128 + l];
                    a0 += wv * f0.x; a1 += wv * f0.y;
                    a2 += wv * f1.x; a3 += wv * f1.y;
                }
                part4[lq][jq] = a0; part4[lq][jq + 1] = a1;
                part4[lq][jq + 2] = a2; part4[lq][jq + 3] = a3;
            }
            barA();
            ctx_s[tid] = (part4[0][tid] + part4[1][tid] + part4[2][tid] + part4[3][tid]) * rinv;
            barA();

            // ---- y_tilde: warp w computes output y=w ----
            {
                const float* wr = wfc_s + w * 264;
                float s = 0.0f;
                #pragma unroll
                for (int k = ln; k < 256; k += 32) s += wr[k] * ctx_s[k];
                s = warp_sum(s);
                if (ln == 0) {
                    #pragma unroll
                    for (int k = 0; k < 8; k++) s += wr[256 + k] * yp_s[k];
                    yt_s[w] = s + bfc_s[w];
                }
            }
        } else {
            // ============ group B: Whh partial gates (h-only) ============
            const int j = tid - 256;
            float4 bv = g_bias4[j];
            float ai = bv.x, af = bv.y, ag = bv.z, ao = bv.w;
            #pragma unroll 4
            for (int k2 = 0; k2 < 128; k2++) {
                uint4 wv = g_whh4[k2 * 256 + j];
                float2 fi = __half22float2(*(__half2*)&wv.x);
                float2 ff = __half22float2(*(__half2*)&wv.y);
                float2 fg = __half22float2(*(__half2*)&wv.z);
                float2 fo = __half22float2(*(__half2*)&wv.w);
                float h0 = hc_s[2 * k2], h1 = hc_s[2 * k2 + 1];
                ai += fi.x * h0 + fi.y * h1;
                af += ff.x * h0 + ff.y * h1;
                ag += fg.x * h0 + fg.y * h1;
                ao += fo.x * h0 + fo.y * h1;
            }
            pg[0][j] = ai; pg[1][j] = af; pg[2][j] = ag; pg[3][j] = ao;
        }
        __syncthreads();   // join A (yt_s, ctx_s) and B (pg)

        // ---- finish gates + cell update (threads 0-255) ----
        if (tid < 256) {
            const int j = tid;
            float gi = pg[0][j], gf = pg[1][j], gg = pg[2][j], go = pg[3][j];
            #pragma unroll
            for (int y = 0; y < 8; y++) {
                float4 wv = g_wih4[y * 256 + j];
                float yv = yt_s[y];
                gi += wv.x * yv; gf += wv.y * yv; gg += wv.z * yv; go += wv.w * yv;
            }
            float cn = fast_sig(gf) * hc_s[256 + j] + fast_sig(gi) * fast_tanh(gg);
            float hn = fast_sig(go) * fast_tanh(cn);
            hc_s[j] = hn;
            hc_s[256 + j] = cn;
        }
        __syncthreads();

        // ---- y_pred(t) = Wfin.[h_new, ctx] + bfin (warps 0-7) ----
        if (w < 8) {
            const float* wr = wfin_s + w * 512;
            float s = 0.0f;
            #pragma unroll
            for (int k = ln; k < 256; k += 32) s += wr[k] * hc_s[k] + wr[256 + k] * ctx_s[k];
            s = warp_sum(s);
            if (ln == 0) {
                float v = s + bfin_s[w];
                out[((size_t)b * T + t) * YD + w] = v;
                yp_s[w] = v;
            }
        }
        __syncthreads();
    }
}

// ---------------- launch ----------------
extern "C" void kernel_launch(void* const* d_in, const int* in_sizes, int n_in,
                              void* d_out, int out_size) {
    const float* x    = (const float*)d_in[0];
    const float* yh   = (const float*)d_in[1];
    const float* W1   = (const float*)d_in[2];
    const float* b1   = (const float*)d_in[3];
    const float* w2   = (const float*)d_in[4];
    const float* Wih  = (const float*)d_in[6];
    const float* Whh  = (const float*)d_in[7];
    const float* bih  = (const float*)d_in[8];
    const float* bhh  = (const float*)d_in[9];
    const float* Wfc  = (const float*)d_in[10];
    const float* bfc  = (const float*)d_in[11];
    const float* Wfin = (const float*)d_in[12];
    const float* bfin = (const float*)d_in[13];
    float* out = (float*)d_out;

    const int T = out_size / (BDIM * YD);

    k_convx<<<2048, 256>>>(x);
    k_convs<<<321, 256>>>(W1, Whh, Wih, bih, bhh);
    k_projmma<<<dim3(2, 512), 256>>>();
    k_decode<<<BDIM, 512>>>(b1, w2, Wfc, bfc, Wfin, bfin, yh, out, T);
}

// round 16
// speedup vs baseline: 2.0438x; 2.0438x over previous
#include <cuda_runtime.h>
#include <cuda_fp16.h>
#include <cstddef>
#include <cstdint>

#define BDIM 128
#define LDIM 512
#define EHD  256
#define DHD  256
#define YD   8

// ---------------- device scratch (static, allocation-free) ----------------
__device__ __half g_projh[(size_t)BDIM * LDIM * EHD]; // 32MB fp16 proj
__device__ __half g_xh[(size_t)BDIM * LDIM * EHD];    // 32MB fp16 x
__device__ __half g_wh[EHD * EHD];                    // W1x fp16 [n][k] (GEMM B)
__device__ uint4  g_whcT8[64 * 256];                  // W1[h,c]: [k8][j], 8 k per j
__device__ uint4  g_whh4[128 * 256];                  // Whh: [k2][j], 4 gates x k-pair
__device__ float4 g_wih4[8 * 256];                    // Wih: [y][j], 4 gates
__device__ float4 g_bias4[256];                       // (bih+bhh) per j, 4 gates

// ---------------- math helpers ----------------
__device__ __forceinline__ float tanh_hw(float x) {
    float y; asm("tanh.approx.f32 %0, %1;" : "=f"(y) : "f"(x)); return y;
}
__device__ __forceinline__ float fast_tanh(float x) { // accurate, for LSTM
    float e = __expf(2.0f * x);
    return 1.0f - __fdividef(2.0f, e + 1.0f);
}
__device__ __forceinline__ float fast_sig(float x) {
    return __fdividef(1.0f, 1.0f + __expf(-x));
}
__device__ __forceinline__ float warp_sum(float v) {
    #pragma unroll
    for (int o = 16; o > 0; o >>= 1) v += __shfl_xor_sync(0xffffffffu, v, o);
    return v;
}
__device__ __forceinline__ float warp_max(float v) {
    #pragma unroll
    for (int o = 16; o > 0; o >>= 1) v = fmaxf(v, __shfl_xor_sync(0xffffffffu, v, o));
    return v;
}
__device__ __forceinline__ void mma_f16(float c[4], const uint32_t a[4],
                                        const uint32_t b[2]) {
    asm volatile(
        "mma.sync.aligned.m16n8k16.row.col.f32.f16.f16.f32 "
        "{%0,%1,%2,%3}, {%4,%5,%6,%7}, {%8,%9}, {%0,%1,%2,%3};\n"
        : "+f"(c[0]), "+f"(c[1]), "+f"(c[2]), "+f"(c[3])
        : "r"(a[0]), "r"(a[1]), "r"(a[2]), "r"(a[3]), "r"(b[0]), "r"(b[1]));
}

// ---------------- converts ----------------
__global__ __launch_bounds__(256) void k_convx(const float* __restrict__ x) {
    const int n4 = (BDIM * LDIM * EHD) / 4;
    for (int i = blockIdx.x * blockDim.x + threadIdx.x; i < n4;
         i += gridDim.x * blockDim.x) {
        float4 v = *(const float4*)(x + (size_t)i * 4);
        __half2 p0 = __floats2half2_rn(v.x, v.y);
        __half2 p1 = __floats2half2_rn(v.z, v.w);
        uint2 o; o.x = *(uint32_t*)&p0; o.y = *(uint32_t*)&p1;
        *(uint2*)(g_xh + (size_t)i * 4) = o;
    }
}

// merged weight converts: blocks [0,64) g_wh; [64,128) whcT8; [128,256) whh4;
// block 256: wih4 + bias4.
__global__ __launch_bounds__(256) void k_convs(const float* __restrict__ W1,
                                               const float* __restrict__ Whh,
                                               const float* __restrict__ Wih,
                                               const float* __restrict__ bih,
                                               const float* __restrict__ bhh) {
    const int blk = blockIdx.x, tid = threadIdx.x;
    if (blk < 64) {
        int i = blk * 256 + tid;              // 16384 float4
        int row = i >> 6, c4 = (i & 63) * 4;
        float4 v = *(const float4*)(W1 + (size_t)row * 768 + 512 + c4);
        __half2 p0 = __floats2half2_rn(v.x, v.y);
        __half2 p1 = __floats2half2_rn(v.z, v.w);
        uint2 o; o.x = *(uint32_t*)&p0; o.y = *(uint32_t*)&p1;
        *(uint2*)(g_wh + (size_t)row * 256 + c4) = o;
    } else if (blk < 128) {
        int idx = (blk - 64) * 256 + tid;     // 16384: k8 x j
        int k8 = idx >> 8, j = idx & 255;
        const float* w = W1 + (size_t)j * 768 + 8 * k8;   // columns [0,512): h then c
        __half2 p0 = __floats2half2_rn(w[0], w[1]);
        __half2 p1 = __floats2half2_rn(w[2], w[3]);
        __half2 p2 = __floats2half2_rn(w[4], w[5]);
        __half2 p3 = __floats2half2_rn(w[6], w[7]);
        uint4 o;
        o.x = *(uint32_t*)&p0; o.y = *(uint32_t*)&p1;
        o.z = *(uint32_t*)&p2; o.w = *(uint32_t*)&p3;
        g_whcT8[idx] = o;
    } else if (blk < 256) {
        int idx = (blk - 128) * 256 + tid;    // 32768: k2 x j
        int k2 = idx >> 8, j = idx & 255;
        uint4 o;
        #pragma unroll
        for (int g = 0; g < 4; g++) {
            const float* w = Whh + (size_t)(g * 256 + j) * 256 + 2 * k2;
            __half2 p = __floats2half2_rn(w[0], w[1]);
            ((uint32_t*)&o)[g] = *(uint32_t*)&p;
        }
        g_whh4[idx] = o;
    } else {
        for (int idx = tid; idx < 2048; idx += 256) {     // wih4: y x j
            int y = idx >> 8, j = idx & 255;
            g_wih4[idx] = make_float4(Wih[(size_t)(0 * 256 + j) * 8 + y],
                                      Wih[(size_t)(1 * 256 + j) * 8 + y],
                                      Wih[(size_t)(2 * 256 + j) * 8 + y],
                                      Wih[(size_t)(3 * 256 + j) * 8 + y]);
        }
        if (tid < 256)
            g_bias4[tid] = make_float4(bih[tid] + bhh[tid],
                                       bih[256 + tid] + bhh[256 + tid],
                                       bih[512 + tid] + bhh[512 + tid],
                                       bih[768 + tid] + bhh[768 + tid]);
    }
}

// ---------------- tensor-core proj GEMM (measured-good, unchanged) -----------
__global__ __launch_bounds__(256) void k_projmma() {
    __shared__ __half As[128][72];
    __shared__ __half Bs[128][72];
    const int bm = blockIdx.y * 128;
    const int bn = blockIdx.x * 128;
    const int tid = threadIdx.x;
    const int wid = tid >> 5, ln = tid & 31;
    const int wm = wid & 3, wn = wid >> 2;
    const int g = ln >> 2, tg2 = (ln & 3) * 2;

    float acc[2][8][4];
    #pragma unroll
    for (int mi = 0; mi < 2; mi++)
        #pragma unroll
        for (int ni = 0; ni < 8; ni++)
            #pragma unroll
            for (int q = 0; q < 4; q++) acc[mi][ni][q] = 0.0f;

    for (int kc = 0; kc < 4; kc++) {
        const int kb = kc * 64;
        #pragma unroll
        for (int it = 0; it < 4; it++) {
            int idx = it * 256 + tid;
            int row = idx >> 3;
            int col8 = (idx & 7) * 8;
            uint4 av = *(const uint4*)(g_xh + (size_t)(bm + row) * 256 + kb + col8);
            uint4 bv = *(const uint4*)(g_wh + (size_t)(bn + row) * 256 + kb + col8);
            *(uint4*)&As[row][col8] = av;
            *(uint4*)&Bs[row][col8] = bv;
        }
        __syncthreads();

        #pragma unroll
        for (int ks = 0; ks < 64; ks += 16) {
            uint32_t a[2][4], bf[8][2];
            #pragma unroll
            for (int mi = 0; mi < 2; mi++) {
                int mb = wm * 32 + mi * 16;
                a[mi][0] = *(const uint32_t*)&As[mb + g][ks + tg2];
                a[mi][1] = *(const uint32_t*)&As[mb + g + 8][ks + tg2];
                a[mi][2] = *(const uint32_t*)&As[mb + g][ks + tg2 + 8];
                a[mi][3] = *(const uint32_t*)&As[mb + g + 8][ks + tg2 + 8];
            }
            #pragma unroll
            for (int ni = 0; ni < 8; ni++) {
                int nb = wn * 64 + ni * 8;
                bf[ni][0] = *(const uint32_t*)&Bs[nb + g][ks + tg2];
                bf[ni][1] = *(const uint32_t*)&Bs[nb + g][ks + tg2 + 8];
            }
            #pragma unroll
            for (int mi = 0; mi < 2; mi++)
                #pragma unroll
                for (int ni = 0; ni < 8; ni++)
                    mma_f16(acc[mi][ni], a[mi], bf[ni]);
        }
        __syncthreads();
    }

    #pragma unroll
    for (int mi = 0; mi < 2; mi++) {
        int r0 = bm + wm * 32 + mi * 16 + g;
        #pragma unroll
        for (int ni = 0; ni < 8; ni++) {
            int col = bn + wn * 64 + ni * 8 + tg2;
            __half2 p0 = __floats2half2_rn(acc[mi][ni][0], acc[mi][ni][1]);
            __half2 p1 = __floats2half2_rn(acc[mi][ni][2], acc[mi][ni][3]);
            *(uint32_t*)&g_projh[(size_t)r0 * 256 + col] = *(uint32_t*)&p0;
            *(uint32_t*)&g_projh[(size_t)(r0 + 8) * 256 + col] = *(uint32_t*)&p1;
        }
    }
}

// ---------------- persistent per-batch decode, 1024 threads ------------------
// One block per batch runs all T steps; every phase uses all 32 warps.
__global__ __launch_bounds__(1024) void k_decode(
    const float* __restrict__ b1v,  const float* __restrict__ w2,
    const float* __restrict__ Wfc,  const float* __restrict__ bfc,
    const float* __restrict__ Wfin, const float* __restrict__ bfin,
    const float* __restrict__ yh,   float* __restrict__ out, int T)
{
    __shared__ float hc_s[512];            // h = [0,256), c = [256,512)
    __shared__ float u_s[EHD], w2_s[EHD], b1_s[EHD];
    __shared__ float sc[LDIM];
    __shared__ float red[64];
    __shared__ float part[16][EHD];        // u partials (4 rows) / ctx partials (16)
    __shared__ float pg[16][EHD];          // gate partials: [kq*4+gate][j]
    __shared__ float ctx_s[EHD];
    __shared__ float yp_s[YD], yt_s[YD], bfc_s[YD], bfin_s[YD];
    __shared__ float ryt[32], ryp[32];

    const int b = blockIdx.x;
    const int tid = threadIdx.x;
    const int w = tid >> 5, ln = tid & 31;

    if (tid < 512) hc_s[tid] = 0.0f;
    else if (tid < 768) { int j = tid - 512; w2_s[j] = w2[j]; }
    else { int j = tid - 768; b1_s[j] = b1v[j]; }
    if (tid < YD) { yp_s[tid] = yh[b * YD + tid]; bfc_s[tid] = bfc[tid]; bfin_s[tid] = bfin[tid]; }
    __syncthreads();

    for (int t = 0; t < T; t++) {
        // ---- u partials: j = tid&255, k-quarter = tid>>8 ----
        {
            const int j = tid & 255, kq = tid >> 8;
            const uint4* wp = g_whcT8 + (size_t)(kq * 16) * 256 + j;
            const float* hv = hc_s + kq * 128;
            float acc = 0.0f;
            #pragma unroll 4
            for (int i = 0; i < 16; i++) {
                uint4 wv = wp[(size_t)i * 256];
                float2 f0 = __half22float2(*(__half2*)&wv.x);
                float2 f1 = __half22float2(*(__half2*)&wv.y);
                float2 f2 = __half22float2(*(__half2*)&wv.z);
                float2 f3 = __half22float2(*(__half2*)&wv.w);
                float4 h0 = *(const float4*)(hv + i * 8);
                float4 h1 = *(const float4*)(hv + i * 8 + 4);
                acc += f0.x * h0.x + f0.y * h0.y + f1.x * h0.z + f1.y * h0.w
                     + f2.x * h1.x + f2.y * h1.y + f3.x * h1.z + f3.y * h1.w;
            }
            part[kq][j] = acc;
        }
        __syncthreads();
        if (tid < 256)
            u_s[tid] = part[0][tid] + part[1][tid] + part[2][tid] + part[3][tid] + b1_s[tid];
        __syncthreads();

        // ---- gate partials (need only h): j x k-quarter ----
        {
            const int j = tid & 255, kq = tid >> 8;
            const uint4* wp = g_whh4 + (size_t)(kq * 32) * 256 + j;
            const float* hv = hc_s + kq * 64;
            float ai = 0.0f, af = 0.0f, ag = 0.0f, ao = 0.0f;
            #pragma unroll 4
            for (int i = 0; i < 32; i++) {
                uint4 wv = wp[(size_t)i * 256];
                float2 fi = __half22float2(*(__half2*)&wv.x);
                float2 ff = __half22float2(*(__half2*)&wv.y);
                float2 fg = __half22float2(*(__half2*)&wv.z);
                float2 fo = __half22float2(*(__half2*)&wv.w);
                float2 hh = *(const float2*)(hv + i * 2);
                ai += fi.x * hh.x + fi.y * hh.y;
                af += ff.x * hh.x + ff.y * hh.y;
                ag += fg.x * hh.x + fg.y * hh.y;
                ao += fo.x * hh.x + fo.y * hh.y;
            }
            pg[kq * 4 + 0][j] = ai; pg[kq * 4 + 1][j] = af;
            pg[kq * 4 + 2][j] = ag; pg[kq * 4 + 3][j] = ao;
        }
        // (no sync needed yet: pg consumed only after later barriers)

        // ---- scores: warp w handles 16 l ----
        {
            const int j0 = ln << 3;
            const float uw0 = u_s[j0],     uw1 = u_s[j0 + 1], uw2 = u_s[j0 + 2], uw3 = u_s[j0 + 3];
            const float uw4 = u_s[j0 + 4], uw5 = u_s[j0 + 5], uw6 = u_s[j0 + 6], uw7 = u_s[j0 + 7];
            const float w20 = w2_s[j0],     w21 = w2_s[j0 + 1], w22 = w2_s[j0 + 2], w23 = w2_s[j0 + 3];
            const float w24 = w2_s[j0 + 4], w25 = w2_s[j0 + 5], w26 = w2_s[j0 + 6], w27 = w2_s[j0 + 7];
            for (int li = 0; li < 16; li++) {
                int l = w * 16 + li;
                const uint4* p = (const uint4*)(g_projh + ((size_t)(b * LDIM + l)) * EHD);
                uint4 pv = p[ln];
                float2 f0 = __half22float2(*(__half2*)&pv.x);
                float2 f1 = __half22float2(*(__half2*)&pv.y);
                float2 f2 = __half22float2(*(__half2*)&pv.z);
                float2 f3 = __half22float2(*(__half2*)&pv.w);
                float s = w20 * tanh_hw(f0.x + uw0) + w21 * tanh_hw(f0.y + uw1)
                        + w22 * tanh_hw(f1.x + uw2) + w23 * tanh_hw(f1.y + uw3)
                        + w24 * tanh_hw(f2.x + uw4) + w25 * tanh_hw(f2.y + uw5)
                        + w26 * tanh_hw(f3.x + uw6) + w27 * tanh_hw(f3.y + uw7);
                s = warp_sum(s);
                if (ln == 0) sc[l] = s;
            }
        }
        __syncthreads();

        // ---- softmax over 512 ----
        float rinv;
        {
            float v = (tid < 512) ? sc[tid] : -1e30f;
            float m = warp_max(v);
            if (ln == 0) red[w] = m;
            __syncthreads();
            float mx = red[0];
            #pragma unroll
            for (int i = 1; i < 32; i++) mx = fmaxf(mx, red[i]);
            float e = 0.0f;
            if (tid < 512) { e = __expf(v - mx); sc[tid] = e; }
            float ss = warp_sum(e);
            if (ln == 0) red[32 + w] = ss;
            __syncthreads();
            float tot = 0.0f;
            #pragma unroll
            for (int i = 0; i < 32; i++) tot += red[32 + i];
            rinv = __fdividef(1.0f, tot);
        }

        // ---- ctx partials: j-quad x l-sixteenth ----
        {
            const int jq = (tid & 63) * 4, ls = tid >> 6;
            const __half* xb = g_xh + ((size_t)(b * LDIM) + ls * 32) * EHD + jq;
            float a0 = 0.0f, a1 = 0.0f, a2 = 0.0f, a3 = 0.0f;
            #pragma unroll 4
            for (int l = 0; l < 32; l++) {
                uint2 pv = *(const uint2*)(xb + (size_t)l * EHD);
                float2 f0 = __half22float2(*(__half2*)&pv.x);
                float2 f1 = __half22float2(*(__half2*)&pv.y);
                float wv = sc[ls * 32 + l];
                a0 += wv * f0.x; a1 += wv * f0.y;
                a2 += wv * f1.x; a3 += wv * f1.y;
            }
            part[ls][jq] = a0; part[ls][jq + 1] = a1;
            part[ls][jq + 2] = a2; part[ls][jq + 3] = a3;
        }
        __syncthreads();
        if (tid < 256) {
            float s = 0.0f;
            #pragma unroll
            for (int i = 0; i < 16; i++) s += part[i][tid];
            ctx_s[tid] = s * rinv;
        }
        __syncthreads();

        // ---- y_tilde: 32 warps, y = w>>2, k-slice = w&3 (64 elems) ----
        {
            const int y = w >> 2, ks = w & 3;
            const float* wr = Wfc + y * 264 + ks * 64;
            const float* cx = ctx_s + ks * 64;
            int k = ln * 2;
            float s = wr[k] * cx[k] + wr[k + 1] * cx[k + 1];
            s = warp_sum(s);
            if (ln == 0) ryt[w] = s;
        }
        __syncthreads();
        if (tid < YD) {
            const float* wr = Wfc + tid * 264;
            float s = ryt[tid * 4] + ryt[tid * 4 + 1] + ryt[tid * 4 + 2] + ryt[tid * 4 + 3];
            #pragma unroll
            for (int k = 0; k < 8; k++) s += wr[256 + k] * yp_s[k];
            yt_s[tid] = s + bfc_s[tid];
        }
        __syncthreads();

        // ---- gates combine + cell update (threads 0-255) ----
        if (tid < 256) {
            const int j = tid;
            float4 bv = g_bias4[j];
            float gi = bv.x + pg[0][j] + pg[4][j] + pg[8][j]  + pg[12][j];
            float gf = bv.y + pg[1][j] + pg[5][j] + pg[9][j]  + pg[13][j];
            float gg = bv.z + pg[2][j] + pg[6][j] + pg[10][j] + pg[14][j];
            float go = bv.w + pg[3][j] + pg[7][j] + pg[11][j] + pg[15][j];
            #pragma unroll
            for (int y = 0; y < 8; y++) {
                float4 wv = g_wih4[y * 256 + j];
                float yv = yt_s[y];
                gi += wv.x * yv; gf += wv.y * yv; gg += wv.z * yv; go += wv.w * yv;
            }
            float cn = fast_sig(gf) * hc_s[256 + j] + fast_sig(gi) * fast_tanh(gg);
            float hn = fast_sig(go) * fast_tanh(cn);
            hc_s[j] = hn;
            hc_s[256 + j] = cn;
        }
        __syncthreads();

        // ---- y_pred: 32 warps, y = w>>2, slice = w&3 (128 of [h,ctx]) ----
        {
            const int y = w >> 2, ks = w & 3;
            const float* wr = Wfin + y * 512 + ks * 128;
            const float* vec = (ks < 2) ? (hc_s + ks * 128) : (ctx_s + (ks - 2) * 128);
            int k = ln * 4;
            float s = wr[k] * vec[k] + wr[k + 1] * vec[k + 1]
                    + wr[k + 2] * vec[k + 2] + wr[k + 3] * vec[k + 3];
            s = warp_sum(s);
            if (ln == 0) ryp[w] = s;
        }
        __syncthreads();
        if (tid < YD) {
            float v = ryp[tid * 4] + ryp[tid * 4 + 1] + ryp[tid * 4 + 2] + ryp[tid * 4 + 3]
                    + bfin_s[tid];
            out[((size_t)b * T + t) * YD + tid] = v;
            yp_s[tid] = v;
        }
        __syncthreads();
    }
}

// ---------------- launch ----------------
extern "C" void kernel_launch(void* const* d_in, const int* in_sizes, int n_in,
                              void* d_out, int out_size) {
    const float* x    = (const float*)d_in[0];
    const float* yh   = (const float*)d_in[1];
    const float* W1   = (const float*)d_in[2];
    const float* b1   = (const float*)d_in[3];
    const float* w2   = (const float*)d_in[4];
    const float* Wih  = (const float*)d_in[6];
    const float* Whh  = (const float*)d_in[7];
    const float* bih  = (const float*)d_in[8];
    const float* bhh  = (const float*)d_in[9];
    const float* Wfc  = (const float*)d_in[10];
    const float* bfc  = (const float*)d_in[11];
    const float* Wfin = (const float*)d_in[12];
    const float* bfin = (const float*)d_in[13];
    float* out = (float*)d_out;

    const int T = out_size / (BDIM * YD);

    k_convx<<<2048, 256>>>(x);
    k_convs<<<257, 256>>>(W1, Whh, Wih, bih, bhh);
    k_projmma<<<dim3(2, 512), 256>>>();
    k_decode<<<BDIM, 1024>>>(b1, w2, Wfc, bfc, Wfin, bfin, yh, out, T);
}

// round 17
// speedup vs baseline: 2.2581x; 1.1048x over previous
#include <cuda_runtime.h>
#include <cuda_fp16.h>
#include <cstddef>
#include <cstdint>

#define BDIM 128
#define LDIM 512
#define EHD  256
#define DHD  256
#define YD   8

// ---------------- device scratch (static, allocation-free) ----------------
__device__ __half g_projh[(size_t)BDIM * LDIM * EHD]; // 32MB fp16 proj
__device__ __half g_xh[(size_t)BDIM * LDIM * EHD];    // 32MB fp16 x
__device__ __half g_wh[EHD * EHD];                    // W1x fp16 [n][k] (GEMM B)
__device__ uint4  g_whcT8[64 * 256];                  // W1[h,c]: [k8][j], 8 k per j
__device__ uint4  g_whh4[128 * 256];                  // Whh: [k2][j], 4 gates x k-pair
__device__ float4 g_wih4[8 * 256];                    // Wih: [y][j], 4 gates
__device__ float4 g_bias4[256];                       // (bih+bhh) per j, 4 gates

// ---------------- math helpers ----------------
__device__ __forceinline__ float tanh_hw(float x) {
    float y; asm("tanh.approx.f32 %0, %1;" : "=f"(y) : "f"(x)); return y;
}
__device__ __forceinline__ float fast_tanh(float x) { // accurate, for LSTM
    float e = __expf(2.0f * x);
    return 1.0f - __fdividef(2.0f, e + 1.0f);
}
__device__ __forceinline__ float fast_sig(float x) {
    return __fdividef(1.0f, 1.0f + __expf(-x));
}
__device__ __forceinline__ float warp_sum(float v) {
    #pragma unroll
    for (int o = 16; o > 0; o >>= 1) v += __shfl_xor_sync(0xffffffffu, v, o);
    return v;
}
__device__ __forceinline__ float warp_max(float v) {
    #pragma unroll
    for (int o = 16; o > 0; o >>= 1) v = fmaxf(v, __shfl_xor_sync(0xffffffffu, v, o));
    return v;
}
__device__ __forceinline__ void mma_f16(float c[4], const uint32_t a[4],
                                        const uint32_t b[2]) {
    asm volatile(
        "mma.sync.aligned.m16n8k16.row.col.f32.f16.f16.f32 "
        "{%0,%1,%2,%3}, {%4,%5,%6,%7}, {%8,%9}, {%0,%1,%2,%3};\n"
        : "+f"(c[0]), "+f"(c[1]), "+f"(c[2]), "+f"(c[3])
        : "r"(a[0]), "r"(a[1]), "r"(a[2]), "r"(a[3]), "r"(b[0]), "r"(b[1]));
}
__device__ __forceinline__ void cp16(uint32_t dst, const void* src) {
    asm volatile("cp.async.ca.shared.global [%0], [%1], 16;\n" :: "r"(dst), "l"(src));
}
__device__ __forceinline__ void cp_commit() {
    asm volatile("cp.async.commit_group;\n" ::: "memory");
}
template<int N> __device__ __forceinline__ void cp_wait() {
    asm volatile("cp.async.wait_group %0;\n" :: "n"(N) : "memory");
}

// ---------------- merged converts: [0,2048) x->fp16; [2048,2305) weights -----
__global__ __launch_bounds__(256) void k_prep(const float* __restrict__ x,
                                              const float* __restrict__ W1,
                                              const float* __restrict__ Whh,
                                              const float* __restrict__ Wih,
                                              const float* __restrict__ bih,
                                              const float* __restrict__ bhh) {
    const int tid = threadIdx.x;
    if (blockIdx.x < 2048) {
        const int n4 = (BDIM * LDIM * EHD) / 4;
        for (int i = blockIdx.x * 256 + tid; i < n4; i += 2048 * 256) {
            float4 v = *(const float4*)(x + (size_t)i * 4);
            __half2 p0 = __floats2half2_rn(v.x, v.y);
            __half2 p1 = __floats2half2_rn(v.z, v.w);
            uint2 o; o.x = *(uint32_t*)&p0; o.y = *(uint32_t*)&p1;
            *(uint2*)(g_xh + (size_t)i * 4) = o;
        }
        return;
    }
    const int blk = blockIdx.x - 2048;
    if (blk < 64) {
        int i = blk * 256 + tid;
        int row = i >> 6, c4 = (i & 63) * 4;
        float4 v = *(const float4*)(W1 + (size_t)row * 768 + 512 + c4);
        __half2 p0 = __floats2half2_rn(v.x, v.y);
        __half2 p1 = __floats2half2_rn(v.z, v.w);
        uint2 o; o.x = *(uint32_t*)&p0; o.y = *(uint32_t*)&p1;
        *(uint2*)(g_wh + (size_t)row * 256 + c4) = o;
    } else if (blk < 128) {
        int idx = (blk - 64) * 256 + tid;     // k8 x j
        int k8 = idx >> 8, j = idx & 255;
        const float* w = W1 + (size_t)j * 768 + 8 * k8;
        __half2 p0 = __floats2half2_rn(w[0], w[1]);
        __half2 p1 = __floats2half2_rn(w[2], w[3]);
        __half2 p2 = __floats2half2_rn(w[4], w[5]);
        __half2 p3 = __floats2half2_rn(w[6], w[7]);
        uint4 o;
        o.x = *(uint32_t*)&p0; o.y = *(uint32_t*)&p1;
        o.z = *(uint32_t*)&p2; o.w = *(uint32_t*)&p3;
        g_whcT8[idx] = o;
    } else if (blk < 256) {
        int idx = (blk - 128) * 256 + tid;    // k2 x j
        int k2 = idx >> 8, j = idx & 255;
        uint4 o;
        #pragma unroll
        for (int g = 0; g < 4; g++) {
            const float* w = Whh + (size_t)(g * 256 + j) * 256 + 2 * k2;
            __half2 p = __floats2half2_rn(w[0], w[1]);
            ((uint32_t*)&o)[g] = *(uint32_t*)&p;
        }
        g_whh4[idx] = o;
    } else {
        for (int idx = tid; idx < 2048; idx += 256) {
            int y = idx >> 8, j = idx & 255;
            g_wih4[idx] = make_float4(Wih[(size_t)(0 * 256 + j) * 8 + y],
                                      Wih[(size_t)(1 * 256 + j) * 8 + y],
                                      Wih[(size_t)(2 * 256 + j) * 8 + y],
                                      Wih[(size_t)(3 * 256 + j) * 8 + y]);
        }
        if (tid < 256)
            g_bias4[tid] = make_float4(bih[tid] + bhh[tid],
                                       bih[256 + tid] + bhh[256 + tid],
                                       bih[512 + tid] + bhh[512 + tid],
                                       bih[768 + tid] + bhh[768 + tid]);
    }
}

// ---------------- tensor-core proj GEMM: double-buffered cp.async ------------
__global__ __launch_bounds__(256) void k_projmma() {
    __shared__ __half As[2][128][40];
    __shared__ __half Bs[2][128][40];
    const int bm = blockIdx.y * 128;
    const int bn = blockIdx.x * 128;
    const int tid = threadIdx.x;
    const int wid = tid >> 5, ln = tid & 31;
    const int wm = wid & 3, wn = wid >> 2;
    const int g = ln >> 2, tg2 = (ln & 3) * 2;

    float acc[2][8][4];
    #pragma unroll
    for (int mi = 0; mi < 2; mi++)
        #pragma unroll
        for (int ni = 0; ni < 8; ni++)
            #pragma unroll
            for (int q = 0; q < 4; q++) acc[mi][ni][q] = 0.0f;

    const int r0l = tid >> 2, c8l = (tid & 3) * 8;           // load coords (2 rows/thread)
    auto issue_chunk = [&](int kc, int buf) {
        #pragma unroll
        for (int it = 0; it < 2; it++) {
            int row = r0l + it * 64;
            uint32_t da = (uint32_t)__cvta_generic_to_shared(&As[buf][row][c8l]);
            uint32_t db = (uint32_t)__cvta_generic_to_shared(&Bs[buf][row][c8l]);
            cp16(da, g_xh + (size_t)(bm + row) * 256 + kc * 32 + c8l);
            cp16(db, g_wh + (size_t)(bn + row) * 256 + kc * 32 + c8l);
        }
        cp_commit();
    };

    issue_chunk(0, 0);
    for (int kc = 0; kc < 8; kc++) {
        const int buf = kc & 1;
        if (kc < 7) { issue_chunk(kc + 1, buf ^ 1); cp_wait<1>(); }
        else        { cp_wait<0>(); }
        __syncthreads();

        #pragma unroll
        for (int ks = 0; ks < 32; ks += 16) {
            uint32_t a[2][4], bf[8][2];
            #pragma unroll
            for (int mi = 0; mi < 2; mi++) {
                int mb = wm * 32 + mi * 16;
                a[mi][0] = *(const uint32_t*)&As[buf][mb + g][ks + tg2];
                a[mi][1] = *(const uint32_t*)&As[buf][mb + g + 8][ks + tg2];
                a[mi][2] = *(const uint32_t*)&As[buf][mb + g][ks + tg2 + 8];
                a[mi][3] = *(const uint32_t*)&As[buf][mb + g + 8][ks + tg2 + 8];
            }
            #pragma unroll
            for (int ni = 0; ni < 8; ni++) {
                int nb = wn * 64 + ni * 8;
                bf[ni][0] = *(const uint32_t*)&Bs[buf][nb + g][ks + tg2];
                bf[ni][1] = *(const uint32_t*)&Bs[buf][nb + g][ks + tg2 + 8];
            }
            #pragma unroll
            for (int mi = 0; mi < 2; mi++)
                #pragma unroll
                for (int ni = 0; ni < 8; ni++)
                    mma_f16(acc[mi][ni], a[mi], bf[ni]);
        }
        __syncthreads();
    }

    #pragma unroll
    for (int mi = 0; mi < 2; mi++) {
        int r0 = bm + wm * 32 + mi * 16 + g;
        #pragma unroll
        for (int ni = 0; ni < 8; ni++) {
            int col = bn + wn * 64 + ni * 8 + tg2;
            __half2 p0 = __floats2half2_rn(acc[mi][ni][0], acc[mi][ni][1]);
            __half2 p1 = __floats2half2_rn(acc[mi][ni][2], acc[mi][ni][3]);
            *(uint32_t*)&g_projh[(size_t)r0 * 256 + col] = *(uint32_t*)&p0;
            *(uint32_t*)&g_projh[(size_t)(r0 + 8) * 256 + col] = *(uint32_t*)&p1;
        }
    }
}

// ---------------- persistent per-batch decode, 1024 threads ------------------
__global__ __launch_bounds__(1024) void k_decode(
    const float* __restrict__ b1v,  const float* __restrict__ w2,
    const float* __restrict__ Wfc,  const float* __restrict__ bfc,
    const float* __restrict__ Wfin, const float* __restrict__ bfin,
    const float* __restrict__ yh,   float* __restrict__ out, int T)
{
    __shared__ float hc_s[512];            // h = [0,256), c = [256,512)
    __shared__ __half2 hh2_s[128], cc2_s[128];   // packed fp16 copies of h, c
    __shared__ float u_s[EHD], w2_s[EHD], b1_s[EHD];
    __shared__ float sc[LDIM];
    __shared__ float red[64];
    __shared__ float part[16][EHD];
    __shared__ float pg[16][EHD];
    __shared__ float ctx_s[EHD];
    __shared__ float yp_s[YD], yt_s[YD], bfc_s[YD], bfin_s[YD];
    __shared__ float ryt[32], ryp[32];

    const int b = blockIdx.x;
    const int tid = threadIdx.x;
    const int w = tid >> 5, ln = tid & 31;
    const __half2 hz = __floats2half2_rn(0.0f, 0.0f);

    if (tid < 512) hc_s[tid] = 0.0f;
    else if (tid < 768) { int j = tid - 512; w2_s[j] = w2[j]; }
    else { int j = tid - 768; b1_s[j] = b1v[j]; }
    if (tid < 128) { hh2_s[tid] = hz; cc2_s[tid] = hz; }
    if (tid < YD) { yp_s[tid] = yh[b * YD + tid]; bfc_s[tid] = bfc[tid]; bfin_s[tid] = bfin[tid]; }
    __syncthreads();

    for (int t = 0; t < T; t++) {
        // ---- u partials (half2): j = tid&255, k-quarter = tid>>8 ----
        {
            const int j = tid & 255, kq = tid >> 8;
            const uint4* wp = g_whcT8 + (size_t)(kq * 16) * 256 + j;
            const uint4* hv4 = ((kq & 2) ? (const uint4*)cc2_s : (const uint4*)hh2_s)
                             + (kq & 1) * 16;
            float accx = 0.0f, accy = 0.0f;
            #pragma unroll
            for (int c = 0; c < 4; c++) {
                __half2 a2 = hz;
                #pragma unroll
                for (int i = 0; i < 4; i++) {
                    int it = c * 4 + i;
                    uint4 wv = wp[(size_t)it * 256];
                    uint4 hraw = hv4[it];
                    const __half2* wh = (const __half2*)&wv;
                    const __half2* hh = (const __half2*)&hraw;
                    a2 = __hfma2(wh[0], hh[0], a2);
                    a2 = __hfma2(wh[1], hh[1], a2);
                    a2 = __hfma2(wh[2], hh[2], a2);
                    a2 = __hfma2(wh[3], hh[3], a2);
                }
                float2 f = __half22float2(a2);
                accx += f.x; accy += f.y;
            }
            part[kq][j] = accx + accy;
        }
        __syncthreads();
        if (tid < 256)
            u_s[tid] = part[0][tid] + part[1][tid] + part[2][tid] + part[3][tid] + b1_s[tid];
        __syncthreads();

        // ---- gate partials (half2, need only h): j x k-quarter ----
        {
            const int j = tid & 255, kq = tid >> 8;
            const uint4* wp = g_whh4 + (size_t)(kq * 32) * 256 + j;
            const uint4* hv4 = (const uint4*)hh2_s + kq * 8;
            float gi = 0.0f, gf = 0.0f, gg = 0.0f, go = 0.0f;
            #pragma unroll
            for (int c = 0; c < 4; c++) {
                __half2 ai2 = hz, af2 = hz, ag2 = hz, ao2 = hz;
                #pragma unroll
                for (int i8 = 0; i8 < 2; i8++) {
                    uint4 hraw = hv4[c * 2 + i8];
                    const __half2* hh = (const __half2*)&hraw;
                    #pragma unroll
                    for (int ii = 0; ii < 4; ii++) {
                        int it = c * 8 + i8 * 4 + ii;
                        uint4 wv = wp[(size_t)it * 256];
                        const __half2* wh = (const __half2*)&wv;
                        ai2 = __hfma2(wh[0], hh[ii], ai2);
                        af2 = __hfma2(wh[1], hh[ii], af2);
                        ag2 = __hfma2(wh[2], hh[ii], ag2);
                        ao2 = __hfma2(wh[3], hh[ii], ao2);
                    }
                }
                float2 f;
                f = __half22float2(ai2); gi += f.x + f.y;
                f = __half22float2(af2); gf += f.x + f.y;
                f = __half22float2(ag2); gg += f.x + f.y;
                f = __half22float2(ao2); go += f.x + f.y;
            }
            pg[kq * 4 + 0][j] = gi; pg[kq * 4 + 1][j] = gf;
            pg[kq * 4 + 2][j] = gg; pg[kq * 4 + 3][j] = go;
        }
        // (no sync needed: pg consumed after later barriers)

        // ---- scores: warp w handles 16 l ----
        {
            const int j0 = ln << 3;
            const float uw0 = u_s[j0],     uw1 = u_s[j0 + 1], uw2 = u_s[j0 + 2], uw3 = u_s[j0 + 3];
            const float uw4 = u_s[j0 + 4], uw5 = u_s[j0 + 5], uw6 = u_s[j0 + 6], uw7 = u_s[j0 + 7];
            const float w20 = w2_s[j0],     w21 = w2_s[j0 + 1], w22 = w2_s[j0 + 2], w23 = w2_s[j0 + 3];
            const float w24 = w2_s[j0 + 4], w25 = w2_s[j0 + 5], w26 = w2_s[j0 + 6], w27 = w2_s[j0 + 7];
            #pragma unroll 2
            for (int li = 0; li < 16; li++) {
                int l = w * 16 + li;
                const uint4* p = (const uint4*)(g_projh + ((size_t)(b * LDIM + l)) * EHD);
                uint4 pv = p[ln];
                float2 f0 = __half22float2(*(__half2*)&pv.x);
                float2 f1 = __half22float2(*(__half2*)&pv.y);
                float2 f2 = __half22float2(*(__half2*)&pv.z);
                float2 f3 = __half22float2(*(__half2*)&pv.w);
                float s = w20 * tanh_hw(f0.x + uw0) + w21 * tanh_hw(f0.y + uw1)
                        + w22 * tanh_hw(f1.x + uw2) + w23 * tanh_hw(f1.y + uw3)
                        + w24 * tanh_hw(f2.x + uw4) + w25 * tanh_hw(f2.y + uw5)
                        + w26 * tanh_hw(f3.x + uw6) + w27 * tanh_hw(f3.y + uw7);
                s = warp_sum(s);
                if (ln == 0) sc[l] = s;
            }
        }
        __syncthreads();

        // ---- softmax over 512 (warp-shuffle combines) ----
        float rinv;
        {
            float v = (tid < 512) ? sc[tid] : -1e30f;
            float m = warp_max(v);
            if (ln == 0) red[w] = m;
            __syncthreads();
            float mx = warp_max(red[ln]);
            float e = 0.0f;
            if (tid < 512) { e = __expf(v - mx); sc[tid] = e; }
            float ss = warp_sum(e);
            if (ln == 0) red[32 + w] = ss;
            __syncthreads();
            float tot = warp_sum(red[32 + ln]);
            rinv = __fdividef(1.0f, tot);
        }

        // ---- ctx partials: j-quad x l-sixteenth ----
        {
            const int jq = (tid & 63) * 4, ls = tid >> 6;
            const __half* xb = g_xh + ((size_t)(b * LDIM) + ls * 32) * EHD + jq;
            float a0 = 0.0f, a1 = 0.0f, a2 = 0.0f, a3 = 0.0f;
            #pragma unroll 4
            for (int l = 0; l < 32; l++) {
                uint2 pv = *(const uint2*)(xb + (size_t)l * EHD);
                float2 f0 = __half22float2(*(__half2*)&pv.x);
                float2 f1 = __half22float2(*(__half2*)&pv.y);
                float wv = sc[ls * 32 + l];
                a0 += wv * f0.x; a1 += wv * f0.y;
                a2 += wv * f1.x; a3 += wv * f1.y;
            }
            part[ls][jq] = a0; part[ls][jq + 1] = a1;
            part[ls][jq + 2] = a2; part[ls][jq + 3] = a3;
        }
        __syncthreads();
        if (tid < 256) {
            float s = 0.0f;
            #pragma unroll
            for (int i = 0; i < 16; i++) s += part[i][tid];
            ctx_s[tid] = s * rinv;
        }
        __syncthreads();

        // ---- y_tilde: 32 warps, y = w>>2, k-slice = w&3 ----
        {
            const int y = w >> 2, ks = w & 3;
            const float* wr = Wfc + y * 264 + ks * 64;
            const float* cx = ctx_s + ks * 64;
            int k = ln * 2;
            float s = wr[k] * cx[k] + wr[k + 1] * cx[k + 1];
            s = warp_sum(s);
            if (ln == 0) ryt[w] = s;
        }
        __syncthreads();
        if (tid < YD) {
            const float* wr = Wfc + tid * 264;
            float s = ryt[tid * 4] + ryt[tid * 4 + 1] + ryt[tid * 4 + 2] + ryt[tid * 4 + 3];
            #pragma unroll
            for (int k = 0; k < 8; k++) s += wr[256 + k] * yp_s[k];
            yt_s[tid] = s + bfc_s[tid];
        }
        __syncthreads();

        // ---- gates combine + cell update + fp16 repack (threads 0-255) ----
        if (tid < 256) {
            const int j = tid;
            float4 bv = g_bias4[j];
            float gi = bv.x + pg[0][j] + pg[4][j] + pg[8][j]  + pg[12][j];
            float gf = bv.y + pg[1][j] + pg[5][j] + pg[9][j]  + pg[13][j];
            float gg = bv.z + pg[2][j] + pg[6][j] + pg[10][j] + pg[14][j];
            float go = bv.w + pg[3][j] + pg[7][j] + pg[11][j] + pg[15][j];
            #pragma unroll
            for (int y = 0; y < 8; y++) {
                float4 wv = g_wih4[y * 256 + j];
                float yv = yt_s[y];
                gi += wv.x * yv; gf += wv.y * yv; gg += wv.z * yv; go += wv.w * yv;
            }
            float cn = fast_sig(gf) * hc_s[256 + j] + fast_sig(gi) * fast_tanh(gg);
            float hn = fast_sig(go) * fast_tanh(cn);
            hc_s[j] = hn;
            hc_s[256 + j] = cn;
            float hn1 = __shfl_down_sync(0xffffffffu, hn, 1);
            float cn1 = __shfl_down_sync(0xffffffffu, cn, 1);
            if ((j & 1) == 0) {
                hh2_s[j >> 1] = __floats2half2_rn(hn, hn1);
                cc2_s[j >> 1] = __floats2half2_rn(cn, cn1);
            }
        }
        __syncthreads();

        // ---- y_pred: 32 warps, y = w>>2, slice = w&3 ----
        {
            const int y = w >> 2, ks = w & 3;
            const float* wr = Wfin + y * 512 + ks * 128;
            const float* vec = (ks < 2) ? (hc_s + ks * 128) : (ctx_s + (ks - 2) * 128);
            int k = ln * 4;
            float s = wr[k] * vec[k] + wr[k + 1] * vec[k + 1]
                    + wr[k + 2] * vec[k + 2] + wr[k + 3] * vec[k + 3];
            s = warp_sum(s);
            if (ln == 0) ryp[w] = s;
        }
        __syncthreads();
        if (tid < YD) {
            float v = ryp[tid * 4] + ryp[tid * 4 + 1] + ryp[tid * 4 + 2] + ryp[tid * 4 + 3]
                    + bfin_s[tid];
            out[((size_t)b * T + t) * YD + tid] = v;
            yp_s[tid] = v;
        }
        __syncthreads();
    }
}

// ---------------- launch ----------------
extern "C" void kernel_launch(void* const* d_in, const int* in_sizes, int n_in,
                              void* d_out, int out_size) {
    const float* x    = (const float*)d_in[0];
    const float* yh   = (const float*)d_in[1];
    const float* W1   = (const float*)d_in[2];
    const float* b1   = (const float*)d_in[3];
    const float* w2   = (const float*)d_in[4];
    const float* Wih  = (const float*)d_in[6];
    const float* Whh  = (const float*)d_in[7];
    const float* bih  = (const float*)d_in[8];
    const float* bhh  = (const float*)d_in[9];
    const float* Wfc  = (const float*)d_in[10];
    const float* bfc  = (const float*)d_in[11];
    const float* Wfin = (const float*)d_in[12];
    const float* bfin = (const float*)d_in[13];
    float* out = (float*)d_out;

    const int T = out_size / (BDIM * YD);

    k_prep<<<2305, 256>>>(x, W1, Whh, Wih, bih, bhh);
    k_projmma<<<dim3(2, 512), 256>>>();
    k_decode<<<BDIM, 1024>>>(b1, w2, Wfc, bfc, Wfin, bfin, yh, out, T);
}